// round 2
// baseline (speedup 1.0000x reference)
#include <cuda_runtime.h>
#include <cuda_bf16.h>

// Fused pipeline: blur(3x3 reflect) -> per-8x8-block T(X)=CXC-SXS -> nonlin
// -> T again -> residual -> Haar(2x2) soft-threshold refine on both branches.
// One CTA = 32x8 pixel strip (four 8x8 blocks) of one (batch,channel) image.

#define H 512
#define W 512

__device__ __forceinline__ float soft05(float x) {
    return copysignf(fmaxf(fabsf(x) - 0.05f, 0.0f), x);
}

__global__ __launch_bounds__(256) void sas_fused_kernel(
    const float* __restrict__ in, float* __restrict__ out)
{
    __shared__ float tile[10][34];   // halo tile (y: -1..8, x: -1..32)
    __shared__ float Xs[8][32];      // working matrix (4 sub-blocks wide)
    __shared__ float B1s[8][32];     // X*C
    __shared__ float B2s[8][32];     // X*S
    __shared__ float Rds[8][32];     // residual for haar stage
    __shared__ float Cs[8][8];
    __shared__ float Ss[8][8];

    const int tx = threadIdx.x;      // 0..31
    const int ty = threadIdx.y;      // 0..7
    const int tid = ty * 32 + tx;
    const int tileX = blockIdx.x * 32;
    const int tileY = blockIdx.y * 8;
    const int z = blockIdx.z;        // combined (batch, channel) 0..95
    const float* img = in + (size_t)z * (H * W);

    // Transform matrices: C[u][x] = cos(2*pi*u*x/8)/sqrt(8), S likewise with sin.
    if (tid < 64) {
        int u = tid >> 3, x = tid & 7;
        float ph = 0.25f * (float)(u * x);
        Cs[u][x] = cospif(ph) * 0.35355339059327373f;
        Ss[u][x] = sinpif(ph) * 0.35355339059327373f;
    }

    // Load 34x10 halo tile with reflect padding.
    for (int i = tid; i < 340; i += 256) {
        int ly = i / 34, lx = i - ly * 34;
        int gy = tileY + ly - 1;
        int gx = tileX + lx - 1;
        gy = (gy < 0) ? -gy : ((gy > H - 1) ? 2 * (H - 1) - gy : gy);
        gx = (gx < 0) ? -gx : ((gx > W - 1) ? 2 * (W - 1) - gx : gx);
        tile[ly][lx] = img[gy * W + gx];
    }
    __syncthreads();

    // Gaussian 3x3, sigma=0.8 (2*sigma^2 = 1.28), normalized.
    const float e1 = expf(-1.0f / 1.28f);
    const float e2 = expf(-2.0f / 1.28f);
    const float inv = 1.0f / (1.0f + 4.0f * e1 + 4.0f * e2);
    const float w0 = inv, w1 = e1 * inv, w2 = e2 * inv;

    const float g =
        w0 * tile[ty + 1][tx + 1] +
        w1 * (tile[ty][tx + 1] + tile[ty + 2][tx + 1] +
              tile[ty + 1][tx] + tile[ty + 1][tx + 2]) +
        w2 * (tile[ty][tx] + tile[ty][tx + 2] +
              tile[ty + 2][tx] + tile[ty + 2][tx + 2]);
    Xs[ty][tx] = g;
    __syncthreads();

    const int sb8 = tx & 24;   // sub-block base column (0,8,16,24)
    const int cl  = tx & 7;    // column within sub-block

    // ---- Forward transform: coeff = C*X*C - S*X*S ----
    float y1 = 0.0f, y2 = 0.0f;
    #pragma unroll
    for (int k = 0; k < 8; k++) {
        float xv = Xs[ty][sb8 + k];
        y1 = fmaf(xv, Cs[k][cl], y1);
        y2 = fmaf(xv, Ss[k][cl], y2);
    }
    B1s[ty][tx] = y1;
    B2s[ty][tx] = y2;
    __syncthreads();

    float coeff = 0.0f;
    #pragma unroll
    for (int k = 0; k < 8; k++) {
        coeff = fmaf(Cs[ty][k], B1s[k][tx], coeff);
        coeff = fmaf(-Ss[ty][k], B2s[k][tx], coeff);
    }

    // ---- Nonlinearity: shrink small coeffs, clip ----
    {
        float ca = fabsf(coeff);
        if (ca < 2.5f) coeff = coeff * (ca * (1.0f / 2.5f));
        coeff = fminf(fmaxf(coeff, -10.0f), 10.0f);
    }
    Xs[ty][tx] = coeff;          // safe: Xs reads completed before prior sync
    __syncthreads();             // covers Xs visibility + B1s/B2s reuse

    // ---- Inverse transform (same linear map) ----
    float z1 = 0.0f, z2 = 0.0f;
    #pragma unroll
    for (int k = 0; k < 8; k++) {
        float xv = Xs[ty][sb8 + k];
        z1 = fmaf(xv, Cs[k][cl], z1);
        z2 = fmaf(xv, Ss[k][cl], z2);
    }
    B1s[ty][tx] = z1;
    B2s[ty][tx] = z2;
    __syncthreads();

    float id = 0.0f;
    #pragma unroll
    for (int k = 0; k < 8; k++) {
        id = fmaf(Cs[ty][k], B1s[k][tx], id);
        id = fmaf(-Ss[ty][k], B2s[k][tx], id);
    }
    const float rd = g - id;

    Xs[ty][tx]  = id;            // safe: Xs reads done before prior sync
    Rds[ty][tx] = rd;
    __syncthreads();

    // ---- Haar refine (2x2 quad local) for both branches ----
    const int y0 = ty & ~1, x0 = tx & ~1;
    const float sy = (ty & 1) ? -1.0f : 1.0f;
    const float sx = (tx & 1) ? -1.0f : 1.0f;

    float aI = Xs[y0][x0],     bI = Xs[y0][x0 + 1];
    float cI = Xs[y0 + 1][x0], dI = Xs[y0 + 1][x0 + 1];
    float LL = (aI + bI + cI + dI) * 0.5f;
    float LH = soft05((aI + bI - cI - dI) * 0.5f);
    float HL = soft05((aI - bI + cI - dI) * 0.5f);
    float HH = soft05((aI - bI - cI + dI) * 0.5f);
    float oI = 0.5f * (LL + sy * LH + sx * HL + sy * sx * HH);

    float aR = Rds[y0][x0],     bR = Rds[y0][x0 + 1];
    float cR = Rds[y0 + 1][x0], dR = Rds[y0 + 1][x0 + 1];
    float LLr = (aR + bR + cR + dR) * 0.5f;
    float LHr = soft05((aR + bR - cR - dR) * 0.5f);
    float HLr = soft05((aR - bR + cR - dR) * 0.5f);
    float HHr = soft05((aR - bR - cR + dR) * 0.5f);
    float oR = 0.5f * (LLr + sy * LHr + sx * HLr + sy * sx * HHr);

    // ---- Output: out[b][ch][y][x], ch = c for I_d_wave, c+3 for R_d_wave ----
    const int bidx = z / 3;
    const int cch  = z - bidx * 3;
    const size_t obase =
        ((size_t)(bidx * 6 + cch) * H + (tileY + ty)) * W + tileX + tx;
    out[obase] = oI;
    out[obase + (size_t)3 * H * W] = oR;
}

extern "C" void kernel_launch(void* const* d_in, const int* in_sizes, int n_in,
                              void* d_out, int out_size) {
    const float* I = (const float*)d_in[0];
    float* out = (float*)d_out;
    dim3 block(32, 8);
    dim3 grid(W / 32, H / 8, 96);   // 16 x 64 x (32 batches * 3 channels)
    sas_fused_kernel<<<grid, block>>>(I, out);
}

// round 4
// speedup vs baseline: 2.5645x; 2.5645x over previous
#include <cuda_runtime.h>
#include <cuda_bf16.h>

#define H 512
#define W 512
#define R2 0.70710678118654752f

// Fused: blur(3x3 reflect) -> T(X)=CXC-SXS per 8x8 block -> nonlin -> T ->
// residual -> Haar soft-threshold refine (both branches).
// Thread = one 8-wide row of one 8x8 block. CTA(256) = 32x64 pixel strip:
// 8 warps (block-rows) x [4 blocks x 8 rows] per warp.

__device__ __forceinline__ float soft05(float x) {
    return copysignf(fmaxf(fabsf(x) - 0.05f, 0.0f), x);
}

// Real 8-pt DFT via butterflies: RE[0..4] (symmetric), SI[0..2] = SI1..SI3
// (antisymmetric, SI0=SI4=0).  RE[u]=sum x_k cos(pi*u*k/4), SI likewise sin.
__device__ __forceinline__ void dft8_real(const float* x, float* RE, float* SI) {
    float s04 = x[0] + x[4], d04 = x[0] - x[4];
    float s26 = x[2] + x[6], d26 = x[2] - x[6];
    float s15 = x[1] + x[5], d15 = x[1] - x[5];
    float s37 = x[3] + x[7], d37 = x[3] - x[7];
    float t1 = s04 + s26, t2 = s15 + s37;
    RE[0] = t1 + t2; RE[4] = t1 - t2; RE[2] = s04 - s26;
    float u = d15 - d37, v = d15 + d37;
    RE[1] = fmaf(R2, u, d04); RE[3] = fmaf(-R2, u, d04);
    SI[0] = fmaf(R2, v, d26);       // SI1
    SI[1] = s15 - s37;              // SI2
    SI[2] = fmaf(R2, v, -d26);      // SI3
}

// o[u] = cosDFT(q)[u] - sinDFT(w)[u],  u = 0..7  (raw, unscaled)
__device__ __forceinline__ void dft8_combine(const float* q, const float* w, float* o) {
    float s04 = q[0] + q[4], d04 = q[0] - q[4];
    float s26 = q[2] + q[6];
    float s15 = q[1] + q[5], d15 = q[1] - q[5];
    float s37 = q[3] + q[7], d37 = q[3] - q[7];
    float t1 = s04 + s26, t2 = s15 + s37;
    float RE0 = t1 + t2, RE4 = t1 - t2, RE2 = s04 - s26;
    float uq = d15 - d37;
    float RE1 = fmaf(R2, uq, d04), RE3 = fmaf(-R2, uq, d04);
    float d26w = w[2] - w[6];
    float vw = (w[1] - w[5]) + (w[3] - w[7]);
    float SI1 = fmaf(R2, vw, d26w);
    float SI2 = (w[1] + w[5]) - (w[3] + w[7]);
    float SI3 = fmaf(R2, vw, -d26w);
    o[0] = RE0;        o[4] = RE4;
    o[1] = RE1 - SI1;  o[7] = RE1 + SI1;
    o[2] = RE2 - SI2;  o[6] = RE2 + SI2;
    o[3] = RE3 - SI3;  o[5] = RE3 + SI3;
}

// Haar DWT -> soft-threshold -> IDWT for one row (partner row via shfl_xor 1).
__device__ __forceinline__ void haar8(const float* v, float* o, bool even) {
    float sy = even ? 1.0f : -1.0f;
    #pragma unroll
    for (int m = 0; m < 4; m++) {
        float e = v[2 * m], f = v[2 * m + 1];
        float pe = __shfl_xor_sync(0xffffffffu, e, 1);
        float pf = __shfl_xor_sync(0xffffffffu, f, 1);
        float a  = even ? e  : pe;
        float bb = even ? f  : pf;
        float c  = even ? pe : e;
        float d  = even ? pf : f;
        float LL = (a + bb + c + d) * 0.5f;
        float LH = soft05((a + bb - c - d) * 0.5f);
        float HL = soft05((a - bb + c - d) * 0.5f);
        float HH = soft05((a - bb - c + d) * 0.5f);
        float p  = LL + sy * LH;
        float qq = HL + sy * HH;
        o[2 * m]     = 0.5f * (p + qq);
        o[2 * m + 1] = 0.5f * (p - qq);
    }
}

__global__ __launch_bounds__(256) void sas_fused2_kernel(
    const float* __restrict__ in, float* __restrict__ out)
{
    __shared__ __align__(16) float buf[32 * 72];  // 32 blocks x (8x8, stride 72)
    __shared__ __align__(16) float tile[66 * 35]; // pitch 35 -> conflict-free

    const int tid = threadIdx.x;
    const int w = tid >> 5;           // warp = block-row (0..7)
    const int l = tid & 31;
    const int b = l >> 3;             // block col within strip (0..3)
    const int r = l & 7;              // row within block (0..7)
    const int tileX = blockIdx.x * 32;
    const int tileY = blockIdx.y * 64;
    const int z = blockIdx.z;
    const float* img = in + (size_t)z * (H * W);

    // ---- Load 66x34 halo tile (reflect padding) ----
    for (int i = tid; i < 66 * 34; i += 256) {
        int ly = i / 34, lx = i - ly * 34;
        int gy = tileY + ly - 1;
        int gx = tileX + lx - 1;
        gy = (gy < 0) ? -gy : ((gy > H - 1) ? 2 * (H - 1) - gy : gy);
        gx = (gx < 0) ? -gx : ((gx > W - 1) ? 2 * (W - 1) - gx : gx);
        tile[ly * 35 + lx] = img[gy * W + gx];
    }
    __syncthreads();

    // ---- Gaussian blur (sigma=0.8) into registers ----
    const float e1 = expf(-0.78125f);       // exp(-1/(2*0.8^2))
    const float e2 = e1 * e1;
    const float inv = 1.0f / (1.0f + 4.0f * (e1 + e2));
    const float w0 = inv, w1 = e1 * inv, w2 = e2 * inv;

    const int Y = w * 8 + r;                 // strip-local row 0..63
    const float* tp = &tile[Y * 35 + b * 8]; // rows Y,Y+1,Y+2; cols x-1..x+8
    float g[8];
    #pragma unroll
    for (int x = 0; x < 8; x++) {
        float A0 = tp[x],       A1 = tp[x + 1],       A2 = tp[x + 2];
        float B0 = tp[35 + x],  B1 = tp[35 + x + 1],  B2 = tp[35 + x + 2];
        float C0 = tp[70 + x],  C1 = tp[70 + x + 1],  C2 = tp[70 + x + 2];
        g[x] = w0 * B1 + w1 * (A1 + C1 + B0 + B2) + w2 * (A0 + A2 + C0 + C2);
    }

    // ---- Forward stage A: row DFT in registers, store compressed ----
    float RE[5], SI[3];
    dft8_real(g, RE, SI);
    float4* s4 = (float4*)&buf[(w * 4 + b) * 72 + r * 8];
    s4[0] = make_float4(RE[0], RE[1], RE[2], RE[3]);
    s4[1] = make_float4(RE[4], SI[0], SI[1], SI[2]);
    __syncthreads();

    // ---- Stage B setup (thread acts as column j = r; same indices reused
    //      for inverse stage B since u = r as well) ----
    const int j = r;
    const int jp = (j <= 4) ? j : 8 - j;                 // RE slot (symmetry)
    const bool z2 = (jp == 0) | (jp == 4);
    const int idx2 = 4 + (z2 ? 1 : jp);                  // SI slot
    const float sgn = z2 ? 0.0f : ((j > 4) ? -1.0f : 1.0f);
    const float* rb = &buf[(w * 4 + b) * 72];

    // ---- Forward stage B: column combine -> coeff -> nonlinearity ----
    float q[8], ww[8];
    #pragma unroll
    for (int k = 0; k < 8; k++) {
        q[k]  = rb[k * 8 + jp];
        ww[k] = sgn * rb[k * 8 + idx2];
    }
    float cf[8];
    dft8_combine(q, ww, cf);
    #pragma unroll
    for (int i = 0; i < 8; i++) {
        float c = cf[i] * 0.125f;                        // fold 1/8 ortho scale
        float ca = fabsf(c);
        float m = fminf(ca * 0.4f, 1.0f);                // shrink below 2.5
        c *= m;
        cf[i] = fminf(fmaxf(c, -10.0f), 10.0f);          // clip
    }

    // ---- Inverse stage A: column DFT in registers ----
    dft8_real(cf, RE, SI);
    __syncthreads();                                     // WAR on buf
    s4[0] = make_float4(RE[0], RE[1], RE[2], RE[3]);
    s4[1] = make_float4(RE[4], SI[0], SI[1], SI[2]);
    __syncthreads();

    // ---- Inverse stage B: row combine (u = r, same jp/idx2/sgn) ----
    #pragma unroll
    for (int k = 0; k < 8; k++) {
        q[k]  = rb[k * 8 + jp];
        ww[k] = sgn * rb[k * 8 + idx2];
    }
    float idraw[8];
    dft8_combine(q, ww, idraw);

    float idv[8], rdv[8];
    #pragma unroll
    for (int x = 0; x < 8; x++) {
        idv[x] = idraw[x] * 0.125f;
        rdv[x] = g[x] - idv[x];
    }

    // ---- Haar refine both branches (row pairs via shfl_xor 1) ----
    const bool even = ((r & 1) == 0);
    float oI[8], oR[8];
    haar8(idv, oI, even);
    haar8(rdv, oR, even);

    // ---- Store: out[b][ch][y][x], ch=c for I-branch, c+3 for R-branch ----
    const int bidx = z / 3;
    const int cch = z - bidx * 3;
    const size_t obase =
        ((size_t)(bidx * 6 + cch) * H + (tileY + Y)) * W + tileX + b * 8;
    float4* o0 = (float4*)(out + obase);
    o0[0] = make_float4(oI[0], oI[1], oI[2], oI[3]);
    o0[1] = make_float4(oI[4], oI[5], oI[6], oI[7]);
    float4* o1 = (float4*)(out + obase + (size_t)3 * H * W);
    o1[0] = make_float4(oR[0], oR[1], oR[2], oR[3]);
    o1[1] = make_float4(oR[4], oR[5], oR[6], oR[7]);
}

extern "C" void kernel_launch(void* const* d_in, const int* in_sizes, int n_in,
                              void* d_out, int out_size) {
    const float* I = (const float*)d_in[0];
    float* out = (float*)d_out;
    dim3 block(256);
    dim3 grid(W / 32, H / 64, 96);
    sas_fused2_kernel<<<grid, block>>>(I, out);
}